// round 17
// baseline (speedup 1.0000x reference)
#include <cuda_runtime.h>

// Problem constants (fixed by the reference: B=4, C=32, H=64, W=64, NW=64)
#define NWC 64
#define NPAIR 32
#define HW_PIX 4096
#define CC 32

// Packed f32x2 FMA: scalar refs; ptxas aliases them into register pairs.
__device__ __forceinline__ void ffma2(float& dx, float& dy,
                                      float ax, float ay,
                                      float bx, float by,
                                      float cx, float cy) {
    asm("{\n\t"
        ".reg .b64 ra, rb, rc, rd;\n\t"
        "mov.b64 ra, {%2, %3};\n\t"
        "mov.b64 rb, {%4, %5};\n\t"
        "mov.b64 rc, {%6, %7};\n\t"
        "fma.rn.f32x2 rd, ra, rb, rc;\n\t"
        "mov.b64 {%0, %1}, rd;\n\t"
        "}"
        : "=f"(dx), "=f"(dy)
        : "f"(ax), "f"(ay), "f"(bx), "f"(by), "f"(cx), "f"(cy));
}

__device__ __forceinline__ float ex2(float a) {
    float r;
    asm("ex2.approx.ftz.f32 %0, %1;" : "=f"(r) : "f"(a));
    return r;
}

__global__ __launch_bounds__(128)
void cplx_gaussian_rbf_kernel(
    const float* __restrict__ x_real, const float* __restrict__ x_imag,
    const float* __restrict__ w_real, const float* __restrict__ w_imag,
    const float* __restrict__ b_real, const float* __restrict__ b_imag,
    const float* __restrict__ mu_real, const float* __restrict__ mu_imag,
    const float* __restrict__ stddev,
    float* __restrict__ out)
{
    // Center-pair coefficient tables: f32x2 lanes carry (center 2p, center 2p+1).
    __shared__ float4 sA[NPAIR];  // {a0_e, a0_o, a1_e, a1_o}
    __shared__ float4 sB[NPAIR];  // {a2_e, a2_o, a3_e, a3_o}
    __shared__ float4 sW[NPAIR];  // {wr_e, wr_o, wi_e, wi_o}

    const int bc   = blockIdx.x >> 3;        // (b*C + c), 0..127
    const int tile = blockIdx.x & 7;         // 8 tiles of 512 pixels per (b,c)
    const int c    = bc & (CC - 1);
    const int tid  = threadIdx.x;

    if (tid < NPAIR) {
        const float LOG2E = 1.4426950408889634f;
        const int n0 = 2 * tid, n1 = 2 * tid + 1;
        // exp(-d2/(2*sigma)) = exp2( a0*s + a1*xr + a2*xi + a3 ),  s = xr^2+xi^2
        float mur0 = mu_real[n0], mui0 = mu_imag[n0];
        float cc0  = LOG2E * 0.5f / stddev[n0];
        float mur1 = mu_real[n1], mui1 = mu_imag[n1];
        float cc1  = LOG2E * 0.5f / stddev[n1];
        sA[tid] = make_float4(-cc0, -cc1, 2.0f * cc0 * mur0, 2.0f * cc1 * mur1);
        sB[tid] = make_float4(2.0f * cc0 * mui0, 2.0f * cc1 * mui1,
                              -cc0 * (mur0 * mur0 + mui0 * mui0),
                              -cc1 * (mur1 * mur1 + mui1 * mui1));
        sW[tid] = make_float4(w_real[c * NWC + n0], w_real[c * NWC + n1],
                              w_imag[c * NWC + n0], w_imag[c * NWC + n1]);
    }
    __syncthreads();

    // 4 consecutive pixels per thread (one float4 load per input).
    const int f4idx    = bc * (HW_PIX / 4) + tile * 128 + tid;  // float4 units
    const int pairBase = f4idx * 2;                              // pixel-pair units

    const float4 xr4 = reinterpret_cast<const float4*>(x_real)[f4idx];
    const float4 xi4 = reinterpret_cast<const float4*>(x_imag)[f4idx];

    float xr[4] = {xr4.x, xr4.y, xr4.z, xr4.w};
    float xi[4] = {xi4.x, xi4.y, xi4.z, xi4.w};

    float s[4];
#pragma unroll
    for (int k = 0; k < 4; ++k)
        s[k] = fmaf(xr[k], xr[k], xi[k] * xi[k]);

    // f32x2 accumulators: lane0 = even centers, lane1 = odd centers.
    float arx[4], ary[4], aix[4], aiy[4];
#pragma unroll
    for (int k = 0; k < 4; ++k) { arx[k] = 0.0f; ary[k] = 0.0f; aix[k] = 0.0f; aiy[k] = 0.0f; }

    // WARP DESYNC: each warp starts the center loop at a different offset so
    // warps' EX2 bursts hit different loop phases — breaks the cross-warp
    // convoy that serializes the MUFU and FMA pipes. Same work, same result
    // (fp reassociation only); LDS stays warp-uniform broadcast.
    const int p0 = ((tid >> 5) << 3);   // warp_id * 8 ∈ {0,8,16,24}

#pragma unroll 4
    for (int i = 0; i < NPAIR; ++i) {
        const int p = (p0 + i) & (NPAIR - 1);
        const float4 A  = sA[p];
        const float4 Bv = sB[p];
        const float4 Wv = sW[p];

#pragma unroll
        for (int k = 0; k < 4; ++k) {
            float gx, gy;
            ffma2(gx, gy, s[k],  s[k],  A.x,  A.y,  Bv.z, Bv.w);  // a0*s + a3
            ffma2(gx, gy, xr[k], xr[k], A.z,  A.w,  gx,   gy);    // + a1*xr
            ffma2(gx, gy, xi[k], xi[k], Bv.x, Bv.y, gx,   gy);    // + a2*xi
            float rx = ex2(gx);
            float ry = ex2(gy);
            ffma2(arx[k], ary[k], rx, ry, Wv.x, Wv.y, arx[k], ary[k]);
            ffma2(aix[k], aiy[k], rx, ry, Wv.z, Wv.w, aix[k], aiy[k]);
        }
    }

    const float br = b_real[c];
    const float bi = b_imag[c];

    // Horizontal add (even+odd centers) + bias; two float4 stores (r,i interleaved).
    float4* out4 = reinterpret_cast<float4*>(out);
#pragma unroll
    for (int q = 0; q < 2; ++q) {
        float4 o;
        o.x = (arx[2*q]   + ary[2*q])   + br;
        o.y = (aix[2*q]   + aiy[2*q])   + bi;
        o.z = (arx[2*q+1] + ary[2*q+1]) + br;
        o.w = (aix[2*q+1] + aiy[2*q+1]) + bi;
        out4[pairBase + q] = o;
    }
}

extern "C" void kernel_launch(void* const* d_in, const int* in_sizes, int n_in,
                              void* d_out, int out_size) {
    const float* x_real  = (const float*)d_in[0];
    const float* x_imag  = (const float*)d_in[1];
    const float* w_real  = (const float*)d_in[2];
    const float* w_imag  = (const float*)d_in[3];
    const float* b_real  = (const float*)d_in[4];
    const float* b_imag  = (const float*)d_in[5];
    const float* mu_real = (const float*)d_in[6];
    const float* mu_imag = (const float*)d_in[7];
    const float* stddev  = (const float*)d_in[8];
    float* out = (float*)d_out;

    // 128 (b,c) pairs * 8 tiles = 1024 blocks; 128 threads; 4 pixels/thread
    cplx_gaussian_rbf_kernel<<<1024, 128>>>(
        x_real, x_imag, w_real, w_imag, b_real, b_imag,
        mu_real, mu_imag, stddev, out);
}